// round 5
// baseline (speedup 1.0000x reference)
#include <cuda_runtime.h>

#define BSZ 32
#define CCH 256
#define NPX 4096
#define REGF 0.01f

// padded smem strides (floats): conflict-free for fragment LDS and staging STS
#define BST 1064            // b-stride: 1064 % 32 == 8
#define CST 33              // c-stride: 33 % 32 == 1
#define HALF 8512           // 8 b-slices * BST
#define BUFSZ (2 * HALF)    // c-half + d-half
// smem total: 2 buffers * BUFSZ floats = 136,192 B

// ---------------------------------------------------------------------------
// Kernel 1: mean over batch. x: [B, C, N], mean: [C, N]. float4 vectorized.
// ---------------------------------------------------------------------------
__global__ void mvg_mean_kernel(const float* __restrict__ x,
                                float* __restrict__ mean) {
    int idx = blockIdx.x * blockDim.x + threadIdx.x;
    const float4* x4 = (const float4*)x;
    float4 s = make_float4(0.f, 0.f, 0.f, 0.f);
    const int stride = CCH * NPX / 4;
#pragma unroll
    for (int b = 0; b < BSZ; b++) {
        float4 v = x4[b * stride + idx];
        s.x += v.x; s.y += v.y; s.z += v.z; s.w += v.w;
    }
    const float inv = 1.0f / BSZ;
    s.x *= inv; s.y *= inv; s.z *= inv; s.w *= inv;
    ((float4*)mean)[idx] = s;
}

// ---------------------------------------------------------------------------
// tf32 mma.sync: D[16,8] += A[16,8] x B[8,8], K = batch dim.
// ---------------------------------------------------------------------------
__device__ __forceinline__ void mma_tf32(float* d, const unsigned* a,
                                         const unsigned* b) {
    asm volatile(
        "mma.sync.aligned.m16n8k8.row.col.f32.tf32.tf32.f32 "
        "{%0,%1,%2,%3}, {%4,%5,%6,%7}, {%8,%9}, {%0,%1,%2,%3};"
        : "+f"(d[0]), "+f"(d[1]), "+f"(d[2]), "+f"(d[3])
        : "r"(a[0]), "r"(a[1]), "r"(a[2]), "r"(a[3]),
          "r"(b[0]), "r"(b[1]));
}

// split f32 into tf32-exact hi (truncate to 10 mantissa bits) + exact lo
__device__ __forceinline__ void split_tf32(float v, unsigned& hi, unsigned& lo) {
    unsigned u = __float_as_uint(v) & 0xFFFFE000u;
    hi = u;
    lo = __float_as_uint(v - __uint_as_float(u));
}

// ---------------------------------------------------------------------------
// Kernel 2: cov[c,d,n] = (sum_b x_c x_d - B m_c m_d)/(B-1) + REG*(c==d)
// Block = 32c x 32d tile pair (upper-tri, mirrored) x one 32-n tile.
// Each warp computes 32c x 32d for its 4 consecutive n via tf32 mma.sync,
// 2-term split (hi*hi + lo*hi + hi*lo) for fp32-class accuracy.
// Staging: LDG.128 -> regs (prefetch under mma) -> STS.32, 2 buffers,
// one __syncthreads per 8-b chunk. Padded layout => zero bank conflicts.
// ---------------------------------------------------------------------------
__global__ __launch_bounds__(256, 1)
void mvg_cov_kernel(const float* __restrict__ x,
                    const float* __restrict__ mean,
                    float* __restrict__ cov) {
    // upper-triangular tile pair (ti <= tj) from blockIdx.x in [0,36)
    int rem = blockIdx.x;
    int ti = 0, row = 8;
    while (rem >= row) { rem -= row; row--; ti++; }
    const int tj = ti + rem;
    const bool diag = (ti == tj);
    const int n0 = blockIdx.y * 32;

    extern __shared__ float sm[];

    const int tid  = threadIdx.x;
    const int w    = tid >> 5;          // warp id: owns n = n0 + w*4 .. +3
    const int lane = tid & 31;
    const int g    = lane >> 2;         // groupID (row within fragment)
    const int t    = lane & 3;          // threadID-in-group (k / col pair)
    const int wn   = w * 4;             // warp's n offset within tile

    // ---- staging helpers: 8 b-slices x 32 c x 32 n per half ----
    float4 pf[8];
    auto ldg_phase = [&](int kb, int rowbase) {
#pragma unroll
        for (int r = 0; r < 8; r++) {
            int f  = r * 256 + tid;
            int bb = f >> 8;
            int c  = (f >> 3) & 31;
            int nn = (f & 7) << 2;
            pf[r] = *(const float4*)&x[((size_t)(kb + bb) * CCH + rowbase + c) * NPX + n0 + nn];
        }
    };
    auto sts_phase = [&](float* dst) {
#pragma unroll
        for (int r = 0; r < 8; r++) {
            int f  = r * 256 + tid;
            int bb = f >> 8;
            int c  = (f >> 3) & 31;
            int nn = (f & 7) << 2;
            float* p = dst + bb * BST + c * CST + nn;
            p[0] = pf[r].x; p[1] = pf[r].y; p[2] = pf[r].z; p[3] = pf[r].w;
        }
    };

    // accumulators: [cblk][dblk][nn][frag]
    float acc[2][4][4][4];
#pragma unroll
    for (int i = 0; i < 2; i++)
#pragma unroll
        for (int j = 0; j < 4; j++)
#pragma unroll
            for (int k = 0; k < 4; k++)
#pragma unroll
                for (int f = 0; f < 4; f++) acc[i][j][k][f] = 0.f;

    // ---- compute nn range [lo,hi) of this warp's 4 n on buffer `buf` ----
    auto compute = [&](const float* buf, int nlo, int nhi) {
        const float* pc = buf;
        const float* pd = diag ? buf : buf + HALF;
        for (int nn = nlo; nn < nhi; nn++) {
            const int nofs = wn + nn;
            unsigned Ah[2][4], Al[2][4], Bh[4][2], Bl[4][2];
#pragma unroll
            for (int cb = 0; cb < 2; cb++) {
                const float* p = pc + t * BST + (cb * 16 + g) * CST + nofs;
                split_tf32(p[0],             Ah[cb][0], Al[cb][0]);
                split_tf32(p[8 * CST],       Ah[cb][1], Al[cb][1]);
                split_tf32(p[4 * BST],       Ah[cb][2], Al[cb][2]);
                split_tf32(p[4 * BST + 8 * CST], Ah[cb][3], Al[cb][3]);
            }
#pragma unroll
            for (int db = 0; db < 4; db++) {
                const float* p = pd + t * BST + (db * 8 + g) * CST + nofs;
                split_tf32(p[0],       Bh[db][0], Bl[db][0]);
                split_tf32(p[4 * BST], Bh[db][1], Bl[db][1]);
            }
#pragma unroll
            for (int cb = 0; cb < 2; cb++)
#pragma unroll
                for (int db = 0; db < 4; db++) {
                    float* d = acc[cb][db][nn];
                    mma_tf32(d, Ah[cb], Bh[db]);   // hi*hi
                    mma_tf32(d, Al[cb], Bh[db]);   // lo*hi
                    mma_tf32(d, Ah[cb], Bl[db]);   // hi*lo
                }
        }
    };

    // ---- prologue: stage chunk 0 ----
    ldg_phase(0, ti * 32);
    sts_phase(sm);
    if (!diag) {
        ldg_phase(0, tj * 32);
        sts_phase(sm + HALF);
    }
    __syncthreads();

    // ---- 4 chunks of 8 b, double-buffered, LDG prefetch under mma ----
#pragma unroll
    for (int ck = 0; ck < 4; ck++) {
        float* cur = sm + (ck & 1) * BUFSZ;
        float* nxt = sm + ((ck + 1) & 1) * BUFSZ;
        if (ck < 3) ldg_phase((ck + 1) * 8, ti * 32);
        compute(cur, 0, 2);
        if (ck < 3) {
            sts_phase(nxt);
            if (!diag) ldg_phase((ck + 1) * 8, tj * 32);
        }
        compute(cur, 2, 4);
        if (ck < 3 && !diag) sts_phase(nxt + HALF);
        __syncthreads();
    }

    // ---- epilogue: mean correction, scale, reg, float4 writes + mirror ----
    const float scale = 1.0f / (BSZ - 1);
    const int gn = n0 + wn;              // multiple of 4
    float4 md[4][2];
#pragma unroll
    for (int db = 0; db < 4; db++)
#pragma unroll
        for (int di = 0; di < 2; di++) {
            int d = tj * 32 + db * 8 + 2 * t + di;
            md[db][di] = *(const float4*)&mean[(size_t)d * NPX + gn];
        }
#pragma unroll
    for (int cb = 0; cb < 2; cb++) {
#pragma unroll
        for (int ci = 0; ci < 2; ci++) {
            int c = ti * 32 + cb * 16 + g + ci * 8;
            float4 mc = *(const float4*)&mean[(size_t)c * NPX + gn];
#pragma unroll
            for (int db = 0; db < 4; db++) {
#pragma unroll
                for (int di = 0; di < 2; di++) {
                    int d = tj * 32 + db * 8 + 2 * t + di;
                    int fi = ci * 2 + di;
                    float4 o;
                    o.x = (acc[cb][db][0][fi] - (float)BSZ * mc.x * md[db][di].x) * scale;
                    o.y = (acc[cb][db][1][fi] - (float)BSZ * mc.y * md[db][di].y) * scale;
                    o.z = (acc[cb][db][2][fi] - (float)BSZ * mc.z * md[db][di].z) * scale;
                    o.w = (acc[cb][db][3][fi] - (float)BSZ * mc.w * md[db][di].w) * scale;
                    if (c == d) { o.x += REGF; o.y += REGF; o.z += REGF; o.w += REGF; }
                    __stcs((float4*)&cov[((size_t)c * CCH + d) * NPX + gn], o);
                    if (!diag)
                        __stcs((float4*)&cov[((size_t)d * CCH + c) * NPX + gn], o);
                }
            }
        }
    }
}

// ---------------------------------------------------------------------------
extern "C" void kernel_launch(void* const* d_in, const int* in_sizes, int n_in,
                              void* d_out, int out_size) {
    const float* x = (const float*)d_in[0];
    float* out  = (float*)d_out;
    float* mean = out;                          // [C, N]
    float* cov  = out + (size_t)CCH * NPX;      // [C, C, N]

    mvg_mean_kernel<<<(CCH * NPX / 4) / 256, 256>>>(x, mean);

    static bool attr_set = false;
    const int smem_bytes = 2 * BUFSZ * 4;       // 136,192 B
    if (!attr_set) {
        cudaFuncSetAttribute(mvg_cov_kernel,
                             cudaFuncAttributeMaxDynamicSharedMemorySize,
                             smem_bytes);
        attr_set = true;
    }
    dim3 grid(36, NPX / 32);                    // (36, 128)
    mvg_cov_kernel<<<grid, 256, smem_bytes>>>(x, mean, cov);
}

// round 6
// speedup vs baseline: 1.4429x; 1.4429x over previous
#include <cuda_runtime.h>

#define BSZ 32
#define CCH 256
#define NPX 4096
#define REGF 0.01f

#define TCR 32            // c-rows per block tile
#define TDR 16            // d-rows per block tile
#define TNN 64            // n per block tile
#define KB  4             // b per chunk
#define NCHUNK (BSZ / KB) // 8
#define CPART (KB * TCR * TNN)          // 8192 floats
#define DPART (KB * TDR * TNN)          // 4096 floats
#define BUF   (CPART + DPART)           // 12288 floats
#define NBUF  4                          // 192 KB total

typedef unsigned long long ull;

// packed fp32x2 FMA (2 FMAs/instr); ptxas never emits from C++.
__device__ __forceinline__ void ffma2(ull& acc, ull a, ull b) {
    asm("fma.rn.f32x2 %0, %1, %2, %0;" : "+l"(acc) : "l"(a), "l"(b));
}
__device__ __forceinline__ unsigned smem_u32(const void* p) {
    return (unsigned)__cvta_generic_to_shared(p);
}
__device__ __forceinline__ void cp16(unsigned s, const float* g) {
    asm volatile("cp.async.cg.shared.global [%0], [%1], 16;" :: "r"(s), "l"(g));
}
#define CP_COMMIT() asm volatile("cp.async.commit_group;" ::: "memory")
#define CP_WAIT2()  asm volatile("cp.async.wait_group 2;" ::: "memory")

// ---------------------------------------------------------------------------
// Kernel 1: mean over batch. x: [B, C, N], mean: [C, N].
// ---------------------------------------------------------------------------
__global__ void mvg_mean_kernel(const float* __restrict__ x,
                                float* __restrict__ mean) {
    int idx = blockIdx.x * blockDim.x + threadIdx.x;
    const float4* x4 = (const float4*)x;
    float4 s = make_float4(0.f, 0.f, 0.f, 0.f);
    const int stride = CCH * NPX / 4;
#pragma unroll
    for (int b = 0; b < BSZ; b++) {
        float4 v = x4[b * stride + idx];
        s.x += v.x; s.y += v.y; s.z += v.z; s.w += v.w;
    }
    const float inv = 1.0f / BSZ;
    s.x *= inv; s.y *= inv; s.z *= inv; s.w *= inv;
    ((float4*)mean)[idx] = s;
}

// ---------------------------------------------------------------------------
// Kernel 2: cov[c,d,n] = (sum_b x_c x_d - B m_c m_d)/(B-1) + REG*(c==d)
// Block tile: 32c x 16d x 64n.  (ci, dj) with dj >= 2*ci; mirrored writes
// fill the lower triangle.  512 threads = 32 n-lanes x 16 (c,d)-warps;
// warp-uniform (c,d) => all LDS are contiguous 256B, zero conflicts.
// Microtile 8c x 4d x 2n packed f32x2 (64 acc regs -> 16 warps/SM).
// Staging: cp.async, 4 buffers, 3 chunks ahead, ONE sync per chunk.
// ---------------------------------------------------------------------------
__global__ __launch_bounds__(512, 1)
void mvg_cov_kernel(const float* __restrict__ x,
                    const float* __restrict__ mean,
                    float* __restrict__ cov) {
    // decode (ci, dj): ci in [0,8), dj in [2*ci, 16)
    int rem = blockIdx.x;
    int ci = 0;
    while (rem >= 16 - 2 * ci) { rem -= 16 - 2 * ci; ci++; }
    const int dj = 2 * ci + rem;
    const bool sub = (dj >> 1) == ci;    // d-rows subset of c-rows
    const int n0 = blockIdx.y * TNN;

    extern __shared__ float sm[];        // NBUF * BUF floats

    const int tid = threadIdx.x;
    const int tn  = tid & 31;            // n-pair lane (2 n per thread)
    const int w   = tid >> 5;
    const int tc  = w & 3;               // 8 c-rows each
    const int td  = w >> 2;              // 4 d-rows each

    // ---- stage chunk ck (b-range [ck*KB, +KB)) into buffer ck%NBUF ----
    auto stage = [&](int ck) {
        float* dst = sm + (ck & (NBUF - 1)) * BUF;
        const int kb = ck * KB;
        // c-part: 4 x (32 rows x 16 float4); bb == r
#pragma unroll
        for (int r = 0; r < 4; r++) {
            int row = tid >> 4;
            int nn4 = (tid & 15) << 2;
            cp16(smem_u32(dst + (r * TCR + row) * TNN + nn4),
                 &x[((size_t)(kb + r) * CCH + ci * TCR + row) * NPX + n0 + nn4]);
        }
        if (!sub) {
            // d-part: 2 x (2bb x 16 rows x 16 float4)
#pragma unroll
            for (int r = 0; r < 2; r++) {
                int bb  = 2 * r + (tid >> 8);
                int row = (tid >> 4) & 15;
                int nn4 = (tid & 15) << 2;
                cp16(smem_u32(dst + CPART + (bb * TDR + row) * TNN + nn4),
                     &x[((size_t)(kb + bb) * CCH + dj * TDR + row) * NPX + n0 + nn4]);
            }
        }
        CP_COMMIT();
    };

    ull acc[8][4];
#pragma unroll
    for (int i = 0; i < 8; i++)
#pragma unroll
        for (int j = 0; j < 4; j++) acc[i][j] = 0ull;

    const int bstr = sub ? TCR : TDR;    // d row-stride inside its region
    const int dofs = sub ? (dj & 1) * TDR * TNN : CPART;

    auto compute = [&](int ck) {
        const float* pc = sm + (ck & (NBUF - 1)) * BUF;
        const float* pa = pc + (tc * 8) * TNN + 2 * tn;
        const float* pb = pc + dofs + (td * 4) * TNN + 2 * tn;
#pragma unroll
        for (int bb = 0; bb < KB; bb++) {
            ull av[8], bv[4];
#pragma unroll
            for (int i = 0; i < 8; i++)
                av[i] = *(const ull*)&pa[(bb * TCR + i) * TNN];
#pragma unroll
            for (int j = 0; j < 4; j++)
                bv[j] = *(const ull*)&pb[(bb * bstr + j) * TNN];
#pragma unroll
            for (int i = 0; i < 8; i++)
#pragma unroll
                for (int j = 0; j < 4; j++)
                    ffma2(acc[i][j], av[i], bv[j]);
        }
    };

    // ---- pipeline: 4 buffers, 3 chunks in flight, one sync per chunk ----
    stage(0); stage(1); stage(2);
#pragma unroll
    for (int ck = 0; ck < NCHUNK; ck++) {
        CP_WAIT2();                 // group ck complete (ck+3 issued, wait<=2)
        __syncthreads();
        compute(ck);
        if (ck + 3 < NCHUNK) stage(ck + 3);
        else CP_COMMIT();           // empty group keeps wait count aligned
    }

    // ---- epilogue: mean correction, scale, reg, write + mirror ----
    const float scale = 1.0f / (BSZ - 1);
    const int n = n0 + 2 * tn;
    float2 md[4];
#pragma unroll
    for (int j = 0; j < 4; j++)
        md[j] = *(const float2*)&mean[(size_t)(dj * TDR + td * 4 + j) * NPX + n];
#pragma unroll
    for (int i = 0; i < 8; i++) {
        const int c = ci * TCR + tc * 8 + i;
        float2 mc = *(const float2*)&mean[(size_t)c * NPX + n];
#pragma unroll
        for (int j = 0; j < 4; j++) {
            const int d = dj * TDR + td * 4 + j;
            ull a = acc[i][j];
            float lo = __uint_as_float((unsigned)(a & 0xffffffffull));
            float hi = __uint_as_float((unsigned)(a >> 32));
            lo = (lo - (float)BSZ * mc.x * md[j].x) * scale;
            hi = (hi - (float)BSZ * mc.y * md[j].y) * scale;
            if (c == d) { lo += REGF; hi += REGF; }
            float2 o = make_float2(lo, hi);
            __stcs((float2*)&cov[((size_t)c * CCH + d) * NPX + n], o);
            __stcs((float2*)&cov[((size_t)d * CCH + c) * NPX + n], o);
        }
    }
}

// ---------------------------------------------------------------------------
extern "C" void kernel_launch(void* const* d_in, const int* in_sizes, int n_in,
                              void* d_out, int out_size) {
    const float* x = (const float*)d_in[0];
    float* out  = (float*)d_out;
    float* mean = out;                          // [C, N]
    float* cov  = out + (size_t)CCH * NPX;      // [C, C, N]

    mvg_mean_kernel<<<(CCH * NPX / 4) / 256, 256>>>(x, mean);

    static bool attr_set = false;
    const int smem_bytes = NBUF * BUF * 4;      // 196,608 B
    if (!attr_set) {
        cudaFuncSetAttribute(mvg_cov_kernel,
                             cudaFuncAttributeMaxDynamicSharedMemorySize,
                             smem_bytes);
        attr_set = true;
    }
    dim3 grid(72, NPX / TNN);                   // (72, 64)
    mvg_cov_kernel<<<grid, 512, smem_bytes>>>(x, mean, cov);
}